// round 3
// baseline (speedup 1.0000x reference)
#include <cuda_runtime.h>
#include <math.h>

#define B_  2
#define C_  128
#define H_  120
#define W_  120
#define L_  14400          // H_*W_
#define DI  160            // D_INNER
#define DS  24             // D_STATE
#define DTR 8              // DT_RANK
#define XD  56             // DTR + 2*DS
#define NC  150            // number of scan chunks
#define LC  96             // chunk length (NC*LC = L_)
#define BL  28800          // B_*L_
#define LOG2E 1.4426950408889634f

// ---------------- scratch (static device globals; no allocation) ----------------
__device__ float g_seq   [BL * C_];        // gathered + layernormed sequence  [B,L,128]
__device__ float g_xz    [BL * 2 * DI];    // in-proj output                   [B,L,320]
__device__ float g_xm    [BL * DI];        // conv+silu output (scan input u)  [B,L,160]
__device__ float g_xdbc  [BL * XD];        // x-proj output (dt | B | C)       [B,L,56]
__device__ float g_delta [BL * DI];        // softplus(dt @ W_dt + b)          [B,L,160]
__device__ float g_S     [BL * DI];        // within-chunk cumsum of delta     [B,L,160]
__device__ float g_ylocal[BL * DI];        // local-scan y                     [B,L,160]
__device__ float g_yout  [BL * DI];        // final scan output (post gate)    [B,L,160]
__device__ float g_outseq[BL * C_];        // out-proj result                  [B,L,128]
__device__ float g_spatT [BL * C_];        // unscrambled spatial^T            [B,HW,128]
__device__ float g_tmp   [BL * C_];        // fusion GEMM result               [B,HW,128]
__device__ float g_hend  [B_ * DI * NC * DS];
__device__ float g_stot  [B_ * DI * NC];
__device__ float g_hstart[B_ * DI * NC * DS];

// ---------------- helpers ----------------
__device__ __forceinline__ float ex2f(float x) {
    float y; asm("ex2.approx.ftz.f32 %0, %1;" : "=f"(y) : "f"(x)); return y;
}
__device__ __forceinline__ float siluf(float x) {
    return x / (1.f + __expf(-x));
}

// ---------------- K1: gather 4-direction cross-scan into seq[B,L,C] ----------------
// seq[b,l,c] = x[b,c,p(c_group,l)]. Tiled 32(c) x 32(p) transpose for coalescing.
__global__ void k_gather_in(const float* __restrict__ x) {
    __shared__ float sx[32][33];
    const int p0 = blockIdx.x * 32;
    const int grp = blockIdx.y;            // channel group 0..3, 32 channels each
    const int cbase = grp * 32;
    const int b = blockIdx.z;
    const int t = threadIdx.x;
    {
        const int pi = t & 31, ci0 = t >> 5;
        #pragma unroll
        for (int r = 0; r < 4; r++) {
            const int c = ci0 + r * 8;
            sx[c][pi] = x[((size_t)(b * C_ + cbase + c)) * L_ + p0 + pi];
        }
    }
    __syncthreads();
    {
        const int ci = t & 31, pi0 = t >> 5;
        #pragma unroll
        for (int r = 0; r < 4; r++) {
            const int pi = pi0 + r * 8;
            const int p = p0 + pi;
            int l;
            if (grp == 0)      l = p;
            else if (grp == 1) l = L_ - 1 - p;
            else {
                const int h = p / W_, w = p % W_;
                const int lt = w * H_ + h;
                l = (grp == 2) ? lt : (L_ - 1 - lt);
            }
            g_seq[((size_t)(b * L_ + l)) * C_ + cbase + ci] = sx[ci][pi];
        }
    }
}

// ---------------- K2: LayerNorm over C=128, in place on g_seq ----------------
__global__ void k_layernorm(const float* __restrict__ nw, const float* __restrict__ nb) {
    const int row = blockIdx.x;           // b*L + l
    const int c = threadIdx.x;            // 0..127
    const float v = g_seq[(size_t)row * C_ + c];
    float s = v, s2 = v * v;
    #pragma unroll
    for (int o = 16; o > 0; o >>= 1) {
        s  += __shfl_xor_sync(~0u, s,  o);
        s2 += __shfl_xor_sync(~0u, s2, o);
    }
    __shared__ float ps[4], ps2[4];
    const int wi = c >> 5;
    if ((c & 31) == 0) { ps[wi] = s; ps2[wi] = s2; }
    __syncthreads();
    s  = ps[0] + ps[1] + ps[2] + ps[3];
    s2 = ps2[0] + ps2[1] + ps2[2] + ps2[3];
    const float mu  = s * (1.f / C_);
    const float var = s2 * (1.f / C_) - mu * mu;
    const float inv = rsqrtf(var + 1e-5f);
    g_seq[(size_t)row * C_ + c] = (v - mu) * inv * nw[c] + nb[c];
}

// ---------------- generic tiled SGEMM body: C[m,n] = sum_k A[m,k]*W[n,k] ----------------
// M = BL (divisible by 64). N,K compile-time. 256 threads, 64x64 tile, 4x4 microtile.
template<int N, int K>
__device__ __forceinline__ void gemm_body(const float* __restrict__ A,
                                          const float* __restrict__ W,
                                          float* __restrict__ C) {
    __shared__ __align__(16) float As[16][68];
    __shared__ __align__(16) float Ws[16][68];
    const int bm = blockIdx.y * 64, bn = blockIdx.x * 64;
    const int t = threadIdx.x;
    const int tx = t & 15, ty = t >> 4;
    float acc[4][4] = {};
    for (int k0 = 0; k0 < K; k0 += 16) {
        #pragma unroll
        for (int r = 0; r < 4; r++) {
            const int idx = t + r * 256;
            const int m = idx >> 4, k = idx & 15;
            As[k][m] = A[(size_t)(bm + m) * K + (k0 + k)];
            Ws[k][m] = (bn + m < N) ? W[(size_t)(bn + m) * K + (k0 + k)] : 0.f;
        }
        __syncthreads();
        #pragma unroll
        for (int kk = 0; kk < 16; kk++) {
            const float4 a4 = *reinterpret_cast<const float4*>(&As[kk][ty * 4]);
            const float4 w4 = *reinterpret_cast<const float4*>(&Ws[kk][tx * 4]);
            const float a[4] = {a4.x, a4.y, a4.z, a4.w};
            const float w[4] = {w4.x, w4.y, w4.z, w4.w};
            #pragma unroll
            for (int i = 0; i < 4; i++)
                #pragma unroll
                for (int j = 0; j < 4; j++)
                    acc[i][j] = fmaf(a[i], w[j], acc[i][j]);
        }
        __syncthreads();
    }
    #pragma unroll
    for (int i = 0; i < 4; i++) {
        const int row = bm + ty * 4 + i;
        #pragma unroll
        for (int j = 0; j < 4; j++) {
            const int col = bn + tx * 4 + j;
            if (col < N) C[(size_t)row * N + col] = acc[i][j];
        }
    }
}

__global__ void k_gemm_in  (const float* __restrict__ W) { gemm_body<2 * DI, C_>(g_seq,  W, g_xz);     }
__global__ void k_gemm_x   (const float* __restrict__ W) { gemm_body<XD,     DI>(g_xm,   W, g_xdbc);   }
__global__ void k_gemm_out (const float* __restrict__ W) { gemm_body<C_,     DI>(g_yout, W, g_outseq); }
__global__ void k_gemm_fuse(const float* __restrict__ W) { gemm_body<C_,     C_>(g_spatT,W, g_tmp);    }

// ---------------- K3: causal depthwise conv (width 4) + SiLU ----------------
__global__ void k_conv_silu(const float* __restrict__ cw, const float* __restrict__ cb) {
    const int i = blockIdx.x * blockDim.x + threadIdx.x;
    if (i >= BL * DI) return;
    const int d = i % DI;
    const int row = i / DI;
    const int l = row % L_;
    float acc = cb[d];
    #pragma unroll
    for (int k = 0; k < 4; k++) {
        const int ll = l - 3 + k;
        if (ll >= 0)
            acc = fmaf(g_xz[((size_t)(row - 3 + k)) * (2 * DI) + d], cw[d * 4 + k], acc);
    }
    g_xm[i] = siluf(acc);
}

// ---------------- K4: delta = softplus(dt @ W_dt^T + b_dt) ----------------
__global__ void k_delta(const float* __restrict__ W_dt, const float* __restrict__ b_dt) {
    const int i = blockIdx.x * blockDim.x + threadIdx.x;
    if (i >= BL * DI) return;
    const int d = i % DI;
    const int row = i / DI;
    float acc = b_dt[d];
    #pragma unroll
    for (int r = 0; r < DTR; r++)
        acc = fmaf(g_xdbc[(size_t)row * XD + r], W_dt[d * DTR + r], acc);
    g_delta[i] = (acc > 25.f) ? acc : log1pf(__expf(acc));
}

// ---------------- K5: scan pass A — local chunk scans ----------------
// grid (NC, B_), 160 threads (one per d). Each thread keeps 24-state in regs.
__global__ void k_scanA(const float* __restrict__ A_log) {
    __shared__ float Bs[LC][DS];
    __shared__ float Cs[LC][DS];
    const int chunk = blockIdx.x, b = blockIdx.y;
    const int d = threadIdx.x;
    const size_t rowbase = (size_t)b * L_ + (size_t)chunk * LC;
    for (int i = d; i < LC * DS; i += DI) {
        const int tt = i / DS, n = i % DS;
        Bs[tt][n] = g_xdbc[(rowbase + tt) * XD + DTR + n];
        Cs[tt][n] = g_xdbc[(rowbase + tt) * XD + DTR + DS + n];
    }
    __syncthreads();

    float A2[DS], h[DS];
    #pragma unroll
    for (int n = 0; n < DS; n++) {
        A2[n] = -__expf(A_log[d * DS + n]) * LOG2E;
        h[n] = 0.f;
    }
    float S = 0.f;
    for (int t = 0; t < LC; t++) {
        const size_t ridx = (rowbase + t) * DI + d;
        const float dt = g_delta[ridx];
        const float u  = g_xm[ridx];
        S += dt;
        g_S[ridx] = S;
        const float du = dt * u;
        float y0 = 0.f, y1 = 0.f, y2 = 0.f, y3 = 0.f;
        #pragma unroll
        for (int n = 0; n < DS; n += 4) {
            float a;
            a = ex2f(dt * A2[n + 0]); h[n + 0] = fmaf(a, h[n + 0], du * Bs[t][n + 0]); y0 = fmaf(h[n + 0], Cs[t][n + 0], y0);
            a = ex2f(dt * A2[n + 1]); h[n + 1] = fmaf(a, h[n + 1], du * Bs[t][n + 1]); y1 = fmaf(h[n + 1], Cs[t][n + 1], y1);
            a = ex2f(dt * A2[n + 2]); h[n + 2] = fmaf(a, h[n + 2], du * Bs[t][n + 2]); y2 = fmaf(h[n + 2], Cs[t][n + 2], y2);
            a = ex2f(dt * A2[n + 3]); h[n + 3] = fmaf(a, h[n + 3], du * Bs[t][n + 3]); y3 = fmaf(h[n + 3], Cs[t][n + 3], y3);
        }
        g_ylocal[ridx] = (y0 + y1) + (y2 + y3);
    }
    const size_t cb = (size_t)(b * DI + d) * NC + chunk;
    #pragma unroll
    for (int n = 0; n < DS; n++) g_hend[cb * DS + n] = h[n];
    g_stot[cb] = S;
}

// ---------------- K6: scan pass B — combine chunk carries ----------------
__global__ void k_scanB(const float* __restrict__ A_log) {
    const int i = blockIdx.x * blockDim.x + threadIdx.x;
    if (i >= B_ * DI * DS) return;
    const int n = i % DS;
    const int d = (i / DS) % DI;
    const int b = i / (DS * DI);
    const float A2 = -__expf(A_log[d * DS + n]) * LOG2E;
    const size_t base = (size_t)(b * DI + d) * NC;
    float carry = 0.f;
    for (int c = 0; c < NC; c++) {
        g_hstart[(base + c) * DS + n] = carry;
        carry = fmaf(ex2f(g_stot[base + c] * A2), carry, g_hend[(base + c) * DS + n]);
    }
}

// ---------------- K7: scan pass C — correction + gate epilogue ----------------
__global__ void k_scanC(const float* __restrict__ A_log, const float* __restrict__ Dp) {
    __shared__ float Cs[LC][DS];
    const int chunk = blockIdx.x, b = blockIdx.y;
    const int d = threadIdx.x;
    const size_t rowbase = (size_t)b * L_ + (size_t)chunk * LC;
    for (int i = d; i < LC * DS; i += DI) {
        const int tt = i / DS, n = i % DS;
        Cs[tt][n] = g_xdbc[(rowbase + tt) * XD + DTR + DS + n];
    }
    __syncthreads();

    float A2[DS], ch0[DS];
    const size_t cb = (size_t)(b * DI + d) * NC + chunk;
    #pragma unroll
    for (int n = 0; n < DS; n++) {
        A2[n]  = -__expf(A_log[d * DS + n]) * LOG2E;
        ch0[n] = g_hstart[cb * DS + n];
    }
    const float Dd = Dp[d];
    for (int t = 0; t < LC; t++) {
        const size_t ridx = (rowbase + t) * DI + d;
        float y = g_ylocal[ridx];
        if (chunk != 0) {
            const float S = g_S[ridx];
            float y0 = 0.f, y1 = 0.f, y2 = 0.f, y3 = 0.f;
            #pragma unroll
            for (int n = 0; n < DS; n += 4) {
                y0 = fmaf(Cs[t][n + 0] * ch0[n + 0], ex2f(A2[n + 0] * S), y0);
                y1 = fmaf(Cs[t][n + 1] * ch0[n + 1], ex2f(A2[n + 1] * S), y1);
                y2 = fmaf(Cs[t][n + 2] * ch0[n + 2], ex2f(A2[n + 2] * S), y2);
                y3 = fmaf(Cs[t][n + 3] * ch0[n + 3], ex2f(A2[n + 3] * S), y3);
            }
            y += (y0 + y1) + (y2 + y3);
        }
        const float u = g_xm[ridx];
        y = fmaf(u, Dd, y);
        const float zz = g_xz[(rowbase + t) * (2 * DI) + DI + d];
        y *= siluf(zz);
        g_yout[ridx] = y;
    }
}

// ---------------- K8: unscramble out_seq -> spatial^T [B, p, c] ----------------
__global__ void k_gather_out() {
    const int i = blockIdx.x * blockDim.x + threadIdx.x;
    if (i >= BL * C_) return;
    const int c = i % C_;
    const int p = (i / C_) % L_;
    const int b = i / (C_ * L_);
    int l;
    if (c < 32)      l = p;
    else if (c < 64) l = L_ - 1 - p;
    else {
        const int h = p / W_, w = p % W_;
        const int lt = w * H_ + h;
        l = (c < 96) ? lt : (L_ - 1 - lt);
    }
    g_spatT[i] = g_outseq[((size_t)(b * L_ + l)) * C_ + c];
}

// ---------------- K9: transpose fusion output + residual ----------------
// out[b,o,p] = x[b,o,p] + scale * g_tmp[(b*L+p)*128 + o]
__global__ void k_final(const float* __restrict__ x, const float* __restrict__ scale,
                        float* __restrict__ out) {
    __shared__ float tt[32][33];
    const int p0 = blockIdx.x * 32, o0 = blockIdx.y * 32, b = blockIdx.z;
    const int t = threadIdx.x;
    {
        const int oi = t & 31, pi0 = t >> 5;
        #pragma unroll
        for (int r = 0; r < 4; r++) {
            const int pi = pi0 + r * 8;
            tt[pi][oi] = g_tmp[((size_t)(b * L_ + p0 + pi)) * C_ + o0 + oi];
        }
    }
    __syncthreads();
    const float s = scale[0];
    {
        const int pi = t & 31, oi0 = t >> 5;
        #pragma unroll
        for (int r = 0; r < 4; r++) {
            const int oi = oi0 + r * 8;
            const size_t idx = ((size_t)(b * C_ + o0 + oi)) * L_ + p0 + pi;
            out[idx] = x[idx] + s * tt[pi][oi];
        }
    }
}

// ---------------- launcher ----------------
extern "C" void kernel_launch(void* const* d_in, const int* in_sizes, int n_in,
                              void* d_out, int out_size) {
    (void)in_sizes; (void)n_in; (void)out_size;
    const float* x        = (const float*)d_in[0];
    const float* norm_w   = (const float*)d_in[1];
    const float* norm_b   = (const float*)d_in[2];
    const float* W_in     = (const float*)d_in[3];
    const float* conv_w   = (const float*)d_in[4];
    const float* conv_b   = (const float*)d_in[5];
    const float* W_x      = (const float*)d_in[6];
    const float* W_dt     = (const float*)d_in[7];
    const float* b_dt     = (const float*)d_in[8];
    const float* A_log    = (const float*)d_in[9];
    const float* Dp       = (const float*)d_in[10];
    const float* W_out    = (const float*)d_in[11];
    const float* fusion_w = (const float*)d_in[12];
    const float* scale    = (const float*)d_in[13];
    float* out = (float*)d_out;

    k_gather_in <<<dim3(L_ / 32, 4, B_), 256>>>(x);
    k_layernorm <<<BL, C_>>>(norm_w, norm_b);
    k_gemm_in   <<<dim3(5, BL / 64), 256>>>(W_in);
    k_conv_silu <<<(BL * DI + 255) / 256, 256>>>(conv_w, conv_b);
    k_gemm_x    <<<dim3(1, BL / 64), 256>>>(W_x);
    k_delta     <<<(BL * DI + 255) / 256, 256>>>(W_dt, b_dt);
    k_scanA     <<<dim3(NC, B_), DI>>>(A_log);
    k_scanB     <<<(B_ * DI * DS + 127) / 128, 128>>>(A_log);
    k_scanC     <<<dim3(NC, B_), DI>>>(A_log, Dp);
    k_gemm_out  <<<dim3(2, BL / 64), 256>>>(W_out);
    k_gather_out<<<(BL * C_ + 255) / 256, 256>>>();
    k_gemm_fuse <<<dim3(2, BL / 64), 256>>>(fusion_w);
    k_final     <<<dim3(L_ / 32, C_ / 32, B_), 256>>>(x, scale, out);
}

// round 9
// speedup vs baseline: 1.0701x; 1.0701x over previous
#include <cuda_runtime.h>
#include <math.h>

#define B_  2
#define C_  128
#define H_  120
#define W_  120
#define L_  14400          // H_*W_
#define DI  160            // D_INNER
#define DS  24             // D_STATE
#define DTR 8              // DT_RANK
#define XD  56             // DTR + 2*DS
#define NC  150            // number of scan chunks
#define LC  96             // chunk length (NC*LC = L_)
#define BL  28800          // B_*L_
#define LOG2E 1.4426950408889634f

// ---------------- scratch (static device globals; no allocation) ----------------
// NOTE: these are ONLY referenced from device code (never passed as kernel
// arguments from the host launcher) — host-side decay of a __device__ symbol
// yields the host shadow address, which on GB300 (ATS) silently reads/writes
// host memory. That was the R4-R8 bug.
__device__ float g_seq   [BL * C_];        // gathered + LN'd sequence         [B,L,128]
__device__ float g_xz    [BL * 2 * DI];    // in-proj output                   [B,L,320]
__device__ float g_xm    [BL * DI];        // conv+silu output (scan input u)  [B,L,160]
__device__ float g_xdbc  [BL * XD];        // x-proj output (dt | B | C)       [B,L,56]
__device__ float g_delta [BL * DI];
__device__ float g_S     [BL * DI];        // within-chunk cumsum of delta
__device__ float g_ylocal[BL * DI];        // local-scan y
__device__ float g_yout  [BL * DI];        // final scan output (post gate)
__device__ float g_outseq[BL * C_];        // out-proj result                  [B,L,128]
__device__ float g_tmp   [BL * C_];        // fusion GEMM result               [B,HW,128]
__device__ float g_hend  [B_ * DI * NC * DS];
__device__ float g_stot  [B_ * DI * NC];
__device__ float g_hstart[B_ * DI * NC * DS];

// ---------------- helpers ----------------
__device__ __forceinline__ float ex2f(float x) {
    float y; asm("ex2.approx.ftz.f32 %0, %1;" : "=f"(y) : "f"(x)); return y;
}
__device__ __forceinline__ float siluf(float x) {
    return x / (1.f + __expf(-x));
}
// packed f32x2 ops (Blackwell FFMA2 path — only reachable via PTX)
__device__ __forceinline__ unsigned long long packf2(float lo, float hi) {
    unsigned long long r;
    asm("mov.b64 %0, {%1, %2};" : "=l"(r) : "f"(lo), "f"(hi));
    return r;
}
__device__ __forceinline__ unsigned long long dupf2(float v) {
    unsigned long long r;
    asm("mov.b64 %0, {%1, %1};" : "=l"(r) : "f"(v));
    return r;
}
__device__ __forceinline__ void fma2(unsigned long long& d, unsigned long long a,
                                     unsigned long long b) {
    asm("fma.rn.f32x2 %0, %1, %2, %0;" : "+l"(d) : "l"(a), "l"(b));
}
__device__ __forceinline__ float lof2(unsigned long long v) {
    float lo, hi;
    asm("mov.b64 {%0, %1}, %2;" : "=f"(lo), "=f"(hi) : "l"(v));
    return lo;
}
__device__ __forceinline__ float hif2(unsigned long long v) {
    float lo, hi;
    asm("mov.b64 {%0, %1}, %2;" : "=f"(lo), "=f"(hi) : "l"(v));
    return hi;
}

// ---------------- K1: gather 4-direction cross-scan into seq[B,L,C] ----------------
__global__ void k_gather_in(const float* __restrict__ x) {
    __shared__ float sx[32][33];
    const int p0 = blockIdx.x * 32;
    const int grp = blockIdx.y;
    const int cbase = grp * 32;
    const int b = blockIdx.z;
    const int t = threadIdx.x;
    {
        const int pi = t & 31, ci0 = t >> 5;
        #pragma unroll
        for (int r = 0; r < 4; r++) {
            const int c = ci0 + r * 8;
            sx[c][pi] = x[((size_t)(b * C_ + cbase + c)) * L_ + p0 + pi];
        }
    }
    __syncthreads();
    {
        const int ci = t & 31, pi0 = t >> 5;
        #pragma unroll
        for (int r = 0; r < 4; r++) {
            const int pi = pi0 + r * 8;
            const int p = p0 + pi;
            int l;
            if (grp == 0)      l = p;
            else if (grp == 1) l = L_ - 1 - p;
            else {
                const int h = p / W_, w = p % W_;
                const int lt = w * H_ + h;
                l = (grp == 2) ? lt : (L_ - 1 - lt);
            }
            g_seq[((size_t)(b * L_ + l)) * C_ + cbase + ci] = sx[ci][pi];
        }
    }
}

// ---------------- K2: LayerNorm over C=128, in place ----------------
__global__ void k_layernorm(const float* __restrict__ nw, const float* __restrict__ nb) {
    const int row = blockIdx.x;
    const int c = threadIdx.x;
    const float v = g_seq[(size_t)row * C_ + c];
    float s = v, s2 = v * v;
    #pragma unroll
    for (int o = 16; o > 0; o >>= 1) {
        s  += __shfl_xor_sync(~0u, s,  o);
        s2 += __shfl_xor_sync(~0u, s2, o);
    }
    __shared__ float ps[4], ps2[4];
    const int wi = c >> 5;
    if ((c & 31) == 0) { ps[wi] = s; ps2[wi] = s2; }
    __syncthreads();
    s  = ps[0] + ps[1] + ps[2] + ps[3];
    s2 = ps2[0] + ps2[1] + ps2[2] + ps2[3];
    const float mu  = s * (1.f / C_);
    const float var = s2 * (1.f / C_) - mu * mu;
    const float inv = rsqrtf(var + 1e-5f);
    g_seq[(size_t)row * C_ + c] = (v - mu) * inv * nw[c] + nb[c];
}

// ---------------- f32x2 SGEMM body: C[m,n] = sum_k A[m,k]*W[n,k] ----------------
// 128(M) x 128(N) block tile, 256 threads, 8x8 microtile split (tm*4 | 64+tm*4) x
// (tn*4 | 64+tn*4). f32x2 accumulators pair adjacent m rows; FFMA2 doubles fp32
// throughput. GATHER applies the 4-direction un-scramble on the A side.
template<int N, int K, bool GATHER>
__device__ __forceinline__ void fgemm_body(const float* __restrict__ A,
                                           const float* __restrict__ Bw,
                                           float* __restrict__ C) {
    constexpr int KC = 16, LD = 132;
    __shared__ float As[KC][LD];   // [k][m]
    __shared__ float Bs[KC][LD];   // [k][n]
    const int bn = blockIdx.x * 128, bm = blockIdx.y * 128;
    const int t = threadIdx.x;
    const int tm = t >> 4, tn = t & 15;

    unsigned long long acc[2][2][8];
    #pragma unroll
    for (int a = 0; a < 2; a++)
        #pragma unroll
        for (int b = 0; b < 2; b++)
            #pragma unroll
            for (int c = 0; c < 8; c++) acc[a][b][c] = 0ull;

    const int lm = t >> 1;                 // load row 0..127
    const int lkq = (t & 1) * 8;           // k offset 0 or 8

    for (int k0 = 0; k0 < K; k0 += KC) {
        // ---- A panel 128m x 16k ----
        float4 fa0, fa1;
        {
            size_t gidx;
            if (GATHER) {
                const int row = bm + lm;
                const int b = row / L_, p = row % L_;
                const int c0 = k0 + lkq;           // 8 channels, one 32-wide group
                const int grp = c0 >> 5;
                int l;
                if (grp == 0)      l = p;
                else if (grp == 1) l = L_ - 1 - p;
                else {
                    const int h = p / W_, w = p % W_;
                    const int lt = w * H_ + h;
                    l = (grp == 2) ? lt : (L_ - 1 - lt);
                }
                gidx = ((size_t)(b * L_ + l)) * C_ + c0;
            } else {
                gidx = (size_t)(bm + lm) * K + k0 + lkq;
            }
            fa0 = *reinterpret_cast<const float4*>(&A[gidx]);
            fa1 = *reinterpret_cast<const float4*>(&A[gidx + 4]);
        }
        // ---- B panel 128n x 16k (zero-pad rows >= N) ----
        float4 fb0 = make_float4(0.f, 0.f, 0.f, 0.f), fb1 = fb0;
        if (bn + lm < N) {
            const size_t bidx = (size_t)(bn + lm) * K + k0 + lkq;
            fb0 = *reinterpret_cast<const float4*>(&Bw[bidx]);
            fb1 = *reinterpret_cast<const float4*>(&Bw[bidx + 4]);
        }
        __syncthreads();
        As[lkq + 0][lm] = fa0.x; As[lkq + 1][lm] = fa0.y;
        As[lkq + 2][lm] = fa0.z; As[lkq + 3][lm] = fa0.w;
        As[lkq + 4][lm] = fa1.x; As[lkq + 5][lm] = fa1.y;
        As[lkq + 6][lm] = fa1.z; As[lkq + 7][lm] = fa1.w;
        Bs[lkq + 0][lm] = fb0.x; Bs[lkq + 1][lm] = fb0.y;
        Bs[lkq + 2][lm] = fb0.z; Bs[lkq + 3][lm] = fb0.w;
        Bs[lkq + 4][lm] = fb1.x; Bs[lkq + 5][lm] = fb1.y;
        Bs[lkq + 6][lm] = fb1.z; Bs[lkq + 7][lm] = fb1.w;
        __syncthreads();

        #pragma unroll
        for (int kk = 0; kk < KC; kk++) {
            const float4 a0 = *reinterpret_cast<const float4*>(&As[kk][tm * 4]);
            const float4 a1 = *reinterpret_cast<const float4*>(&As[kk][64 + tm * 4]);
            const float4 b0 = *reinterpret_cast<const float4*>(&Bs[kk][tn * 4]);
            const float4 b1 = *reinterpret_cast<const float4*>(&Bs[kk][64 + tn * 4]);
            const unsigned long long ap[2][2] = {
                {packf2(a0.x, a0.y), packf2(a0.z, a0.w)},
                {packf2(a1.x, a1.y), packf2(a1.z, a1.w)}};
            const unsigned long long bd[8] = {
                dupf2(b0.x), dupf2(b0.y), dupf2(b0.z), dupf2(b0.w),
                dupf2(b1.x), dupf2(b1.y), dupf2(b1.z), dupf2(b1.w)};
            #pragma unroll
            for (int mg = 0; mg < 2; mg++)
                #pragma unroll
                for (int mp = 0; mp < 2; mp++)
                    #pragma unroll
                    for (int n = 0; n < 8; n++)
                        fma2(acc[mg][mp][n], ap[mg][mp], bd[n]);
        }
    }

    #pragma unroll
    for (int mg = 0; mg < 2; mg++) {
        #pragma unroll
        for (int mp = 0; mp < 2; mp++) {
            const int m0 = bm + mg * 64 + tm * 4 + mp * 2;
            #pragma unroll
            for (int ng = 0; ng < 2; ng++) {
                const int n0 = bn + ng * 64 + tn * 4;
                if (n0 < N) {
                    const float4 rlo = make_float4(
                        lof2(acc[mg][mp][ng * 4 + 0]), lof2(acc[mg][mp][ng * 4 + 1]),
                        lof2(acc[mg][mp][ng * 4 + 2]), lof2(acc[mg][mp][ng * 4 + 3]));
                    const float4 rhi = make_float4(
                        hif2(acc[mg][mp][ng * 4 + 0]), hif2(acc[mg][mp][ng * 4 + 1]),
                        hif2(acc[mg][mp][ng * 4 + 2]), hif2(acc[mg][mp][ng * 4 + 3]));
                    *reinterpret_cast<float4*>(&C[(size_t)m0 * N + n0]) = rlo;
                    *reinterpret_cast<float4*>(&C[(size_t)(m0 + 1) * N + n0]) = rhi;
                }
            }
        }
    }
}

// Wrappers: globals bound in DEVICE code (the critical fix).
__global__ void __launch_bounds__(256) k_gemm_in(const float* __restrict__ W) {
    fgemm_body<2 * DI, C_, false>(g_seq, W, g_xz);
}
__global__ void __launch_bounds__(256) k_gemm_out(const float* __restrict__ W) {
    fgemm_body<C_, DI, false>(g_yout, W, g_outseq);
}
__global__ void __launch_bounds__(256) k_gemm_fuse(const float* __restrict__ W) {
    fgemm_body<C_, C_, true>(g_outseq, W, g_tmp);
}

// ---------------- fp32 SGEMM (R2-verbatim) for the x-proj -----------
template<int N, int K>
__device__ __forceinline__ void gemm_body(const float* __restrict__ A,
                                          const float* __restrict__ W,
                                          float* __restrict__ C) {
    __shared__ __align__(16) float As[16][68];
    __shared__ __align__(16) float Ws[16][68];
    const int bm = blockIdx.y * 64, bn = blockIdx.x * 64;
    const int t = threadIdx.x;
    const int tx = t & 15, ty = t >> 4;
    float acc[4][4] = {};
    for (int k0 = 0; k0 < K; k0 += 16) {
        #pragma unroll
        for (int r = 0; r < 4; r++) {
            const int idx = t + r * 256;
            const int m = idx >> 4, k = idx & 15;
            As[k][m] = A[(size_t)(bm + m) * K + (k0 + k)];
            Ws[k][m] = (bn + m < N) ? W[(size_t)(bn + m) * K + (k0 + k)] : 0.f;
        }
        __syncthreads();
        #pragma unroll
        for (int kk = 0; kk < 16; kk++) {
            const float4 a4 = *reinterpret_cast<const float4*>(&As[kk][ty * 4]);
            const float4 w4 = *reinterpret_cast<const float4*>(&Ws[kk][tx * 4]);
            const float a[4] = {a4.x, a4.y, a4.z, a4.w};
            const float w[4] = {w4.x, w4.y, w4.z, w4.w};
            #pragma unroll
            for (int i = 0; i < 4; i++)
                #pragma unroll
                for (int j = 0; j < 4; j++)
                    acc[i][j] = fmaf(a[i], w[j], acc[i][j]);
        }
        __syncthreads();
    }
    #pragma unroll
    for (int i = 0; i < 4; i++) {
        const int row = bm + ty * 4 + i;
        #pragma unroll
        for (int j = 0; j < 4; j++) {
            const int col = bn + tx * 4 + j;
            if (col < N) C[(size_t)row * N + col] = acc[i][j];
        }
    }
}
__global__ void k_gemm_x(const float* __restrict__ W) { gemm_body<XD, DI>(g_xm, W, g_xdbc); }

// ---------------- K3: causal depthwise conv (width 4) + SiLU ----------------
__global__ void k_conv_silu(const float* __restrict__ cw, const float* __restrict__ cb) {
    const int i = blockIdx.x * blockDim.x + threadIdx.x;
    if (i >= BL * DI) return;
    const int d = i % DI;
    const int row = i / DI;
    const int l = row % L_;
    float acc = cb[d];
    #pragma unroll
    for (int k = 0; k < 4; k++) {
        const int ll = l - 3 + k;
        if (ll >= 0)
            acc = fmaf(g_xz[((size_t)(row - 3 + k)) * (2 * DI) + d], cw[d * 4 + k], acc);
    }
    g_xm[i] = siluf(acc);
}

// ---------------- K4: delta = softplus(dt @ W_dt^T + b_dt) ----------------
__global__ void k_delta(const float* __restrict__ W_dt, const float* __restrict__ b_dt) {
    const int i = blockIdx.x * blockDim.x + threadIdx.x;
    if (i >= BL * DI) return;
    const int d = i % DI;
    const int row = i / DI;
    float acc = b_dt[d];
    #pragma unroll
    for (int r = 0; r < DTR; r++)
        acc = fmaf(g_xdbc[(size_t)row * XD + r], W_dt[d * DTR + r], acc);
    g_delta[i] = (acc > 25.f) ? acc : log1pf(__expf(acc));
}

// ---------------- K5: scan pass A — local chunk scans ----------------
__global__ void k_scanA(const float* __restrict__ A_log) {
    __shared__ float Bs[LC][DS];
    __shared__ float Cs[LC][DS];
    const int chunk = blockIdx.x, b = blockIdx.y;
    const int d = threadIdx.x;
    const size_t rowbase = (size_t)b * L_ + (size_t)chunk * LC;
    for (int i = d; i < LC * DS; i += DI) {
        const int tt = i / DS, n = i % DS;
        Bs[tt][n] = g_xdbc[(rowbase + tt) * XD + DTR + n];
        Cs[tt][n] = g_xdbc[(rowbase + tt) * XD + DTR + DS + n];
    }
    __syncthreads();

    float A2[DS], h[DS];
    #pragma unroll
    for (int n = 0; n < DS; n++) {
        A2[n] = -__expf(A_log[d * DS + n]) * LOG2E;
        h[n] = 0.f;
    }
    float S = 0.f;
    for (int t = 0; t < LC; t++) {
        const size_t ridx = (rowbase + t) * DI + d;
        const float dt = g_delta[ridx];
        const float u  = g_xm[ridx];
        S += dt;
        g_S[ridx] = S;
        const float du = dt * u;
        float y0 = 0.f, y1 = 0.f, y2 = 0.f, y3 = 0.f;
        #pragma unroll
        for (int n = 0; n < DS; n += 4) {
            float a;
            a = ex2f(dt * A2[n + 0]); h[n + 0] = fmaf(a, h[n + 0], du * Bs[t][n + 0]); y0 = fmaf(h[n + 0], Cs[t][n + 0], y0);
            a = ex2f(dt * A2[n + 1]); h[n + 1] = fmaf(a, h[n + 1], du * Bs[t][n + 1]); y1 = fmaf(h[n + 1], Cs[t][n + 1], y1);
            a = ex2f(dt * A2[n + 2]); h[n + 2] = fmaf(a, h[n + 2], du * Bs[t][n + 2]); y2 = fmaf(h[n + 2], Cs[t][n + 2], y2);
            a = ex2f(dt * A2[n + 3]); h[n + 3] = fmaf(a, h[n + 3], du * Bs[t][n + 3]); y3 = fmaf(h[n + 3], Cs[t][n + 3], y3);
        }
        g_ylocal[ridx] = (y0 + y1) + (y2 + y3);
    }
    const size_t cb = (size_t)(b * DI + d) * NC + chunk;
    #pragma unroll
    for (int n = 0; n < DS; n++) g_hend[cb * DS + n] = h[n];
    g_stot[cb] = S;
}

// ---------------- K6: scan pass B — combine chunk carries ----------------
__global__ void k_scanB(const float* __restrict__ A_log) {
    const int i = blockIdx.x * blockDim.x + threadIdx.x;
    if (i >= B_ * DI * DS) return;
    const int n = i % DS;
    const int d = (i / DS) % DI;
    const int b = i / (DS * DI);
    const float A2 = -__expf(A_log[d * DS + n]) * LOG2E;
    const size_t base = (size_t)(b * DI + d) * NC;
    float carry = 0.f;
    for (int c = 0; c < NC; c++) {
        g_hstart[(base + c) * DS + n] = carry;
        carry = fmaf(ex2f(g_stot[base + c] * A2), carry, g_hend[(base + c) * DS + n]);
    }
}

// ---------------- K7: scan pass C — correction + gate epilogue ----------------
__global__ void k_scanC(const float* __restrict__ A_log, const float* __restrict__ Dp) {
    __shared__ float Cs[LC][DS];
    const int chunk = blockIdx.x, b = blockIdx.y;
    const int d = threadIdx.x;
    const size_t rowbase = (size_t)b * L_ + (size_t)chunk * LC;
    for (int i = d; i < LC * DS; i += DI) {
        const int tt = i / DS, n = i % DS;
        Cs[tt][n] = g_xdbc[(rowbase + tt) * XD + DTR + DS + n];
    }
    __syncthreads();

    float A2[DS], ch0[DS];
    const size_t cb = (size_t)(b * DI + d) * NC + chunk;
    #pragma unroll
    for (int n = 0; n < DS; n++) {
        A2[n]  = -__expf(A_log[d * DS + n]) * LOG2E;
        ch0[n] = g_hstart[cb * DS + n];
    }
    const float Dd = Dp[d];
    for (int t = 0; t < LC; t++) {
        const size_t ridx = (rowbase + t) * DI + d;
        float y = g_ylocal[ridx];
        if (chunk != 0) {
            const float S = g_S[ridx];
            float y0 = 0.f, y1 = 0.f, y2 = 0.f, y3 = 0.f;
            #pragma unroll
            for (int n = 0; n < DS; n += 4) {
                y0 = fmaf(Cs[t][n + 0] * ch0[n + 0], ex2f(A2[n + 0] * S), y0);
                y1 = fmaf(Cs[t][n + 1] * ch0[n + 1], ex2f(A2[n + 1] * S), y1);
                y2 = fmaf(Cs[t][n + 2] * ch0[n + 2], ex2f(A2[n + 2] * S), y2);
                y3 = fmaf(Cs[t][n + 3] * ch0[n + 3], ex2f(A2[n + 3] * S), y3);
            }
            y += (y0 + y1) + (y2 + y3);
        }
        const float u = g_xm[ridx];
        y = fmaf(u, Dd, y);
        const float zz = g_xz[(rowbase + t) * (2 * DI) + DI + d];
        y *= siluf(zz);
        g_yout[ridx] = y;
    }
}

// ---------------- K9: transpose fusion output + residual ----------------
__global__ void k_final(const float* __restrict__ x, const float* __restrict__ scale,
                        float* __restrict__ out) {
    __shared__ float tt[32][33];
    const int p0 = blockIdx.x * 32, o0 = blockIdx.y * 32, b = blockIdx.z;
    const int t = threadIdx.x;
    {
        const int oi = t & 31, pi0 = t >> 5;
        #pragma unroll
        for (int r = 0; r < 4; r++) {
            const int pi = pi0 + r * 8;
            tt[pi][oi] = g_tmp[((size_t)(b * L_ + p0 + pi)) * C_ + o0 + oi];
        }
    }
    __syncthreads();
    const float s = scale[0];
    {
        const int pi = t & 31, oi0 = t >> 5;
        #pragma unroll
        for (int r = 0; r < 4; r++) {
            const int oi = oi0 + r * 8;
            const size_t idx = ((size_t)(b * C_ + o0 + oi)) * L_ + p0 + pi;
            out[idx] = x[idx] + s * tt[pi][oi];
        }
    }
}

// ---------------- launcher ----------------
extern "C" void kernel_launch(void* const* d_in, const int* in_sizes, int n_in,
                              void* d_out, int out_size) {
    (void)in_sizes; (void)n_in; (void)out_size;
    const float* x        = (const float*)d_in[0];
    const float* norm_w   = (const float*)d_in[1];
    const float* norm_b   = (const float*)d_in[2];
    const float* W_in     = (const float*)d_in[3];
    const float* conv_w   = (const float*)d_in[4];
    const float* conv_b   = (const float*)d_in[5];
    const float* W_x      = (const float*)d_in[6];
    const float* W_dt     = (const float*)d_in[7];
    const float* b_dt     = (const float*)d_in[8];
    const float* A_log    = (const float*)d_in[9];
    const float* Dp       = (const float*)d_in[10];
    const float* W_out    = (const float*)d_in[11];
    const float* fusion_w = (const float*)d_in[12];
    const float* scale    = (const float*)d_in[13];
    float* out = (float*)d_out;

    k_gather_in <<<dim3(L_ / 32, 4, B_), 256>>>(x);
    k_layernorm <<<BL, C_>>>(norm_w, norm_b);
    k_gemm_in   <<<dim3(3, BL / 128), 256>>>(W_in);
    k_conv_silu <<<(BL * DI + 255) / 256, 256>>>(conv_w, conv_b);
    k_gemm_x    <<<dim3(1, BL / 64), 256>>>(W_x);
    k_delta     <<<(BL * DI + 255) / 256, 256>>>(W_dt, b_dt);
    k_scanA     <<<dim3(NC, B_), DI>>>(A_log);
    k_scanB     <<<(B_ * DI * DS + 127) / 128, 128>>>(A_log);
    k_scanC     <<<dim3(NC, B_), DI>>>(A_log, Dp);
    k_gemm_out  <<<dim3(1, BL / 128), 256>>>(W_out);
    k_gemm_fuse <<<dim3(1, BL / 128), 256>>>(fusion_w);
    k_final     <<<dim3(L_ / 32, C_ / 32, B_), 256>>>(x, scale, out);
}